// round 16
// baseline (speedup 1.0000x reference)
#include <cuda_runtime.h>
#include <cstdint>
#include <math.h>

#define JN 24
#define EPSF 1e-8f
#define TPB 96

// R16 = R15 (best, 66.3us) with TPB=96: staging 35.3KB/CTA -> 6 CTAs/SM,
// 18 warps/SM (was 4 CTAs / 16 warps). Six phase-staggered streams per SM
// smooth the burst/wait/compute cycle; 3-warp CTAs keep per-CTA overhead
// amortized (the R14 TPB=64 failure mode was 2-warp CTAs at 2x CTA count).
// Body identical to R15: cp.async staging, rsqrt normalization, v8 loads,
// rolling-8 v8 stores.

__device__ __forceinline__ void stg256(float* p, const float* v) {
    asm volatile(
        "st.global.v8.f32 [%0], {%1,%2,%3,%4,%5,%6,%7,%8};"
        :: "l"(p),
           "f"(v[0]), "f"(v[1]), "f"(v[2]), "f"(v[3]),
           "f"(v[4]), "f"(v[5]), "f"(v[6]), "f"(v[7])
        : "memory");
}

__device__ __forceinline__ void ldg256(const float* p, float* v) {
    asm(
        "ld.global.v8.f32 {%0,%1,%2,%3,%4,%5,%6,%7}, [%8];"
        : "=f"(v[0]), "=f"(v[1]), "=f"(v[2]), "=f"(v[3]),
          "=f"(v[4]), "=f"(v[5]), "=f"(v[6]), "=f"(v[7])
        : "l"(p));
}

__device__ __forceinline__ void cp_async16(unsigned int smem_dst, const void* gsrc) {
    asm volatile("cp.async.cg.shared.global [%0], [%1], 16;"
                 :: "r"(smem_dst), "l"(gsrc) : "memory");
}

__global__ __launch_bounds__(TPB) void fk_kernel(
    const float4* __restrict__ rootq,   // [B,4]  (w,x,y,z)
    const float*  __restrict__ rootp,   // [B,3]
    const float*  __restrict__ localq,  // [B,J,4] as floats
    const float*  __restrict__ bl,      // [B,J]
    const float*  __restrict__ restd,   // [J,3]
    float*        __restrict__ out,     // [B,J,3]
    int nbatch)
{
    __shared__ float4 sq[TPB * 23];     // quats 1..23 per element, 368B rows
    __shared__ float  sdir[JN * 3];

    const int tid = threadIdx.x;
    if (tid < JN * 3) sdir[tid] = restd[tid];

    const int blk0 = blockIdx.x * TPB;
    const int b    = blk0 + tid;
    const bool active = (b < nbatch);

    // ---- Stage local quats 1..23 for all TPB elements via cp.async ----
    {
        unsigned int sq_base;
        asm("{ .reg .u64 t; cvta.to.shared.u64 t, %1; cvt.u32.u64 %0, t; }"
            : "=r"(sq_base) : "l"(sq));
        const float* lqb = localq + (size_t)blk0 * (JN * 4);

        #pragma unroll
        for (int k = 0; k < 23; k++) {
            int g = tid + k * TPB;          // 0..TPB*23-1
            int e = g / 23;
            int j = 1 + (g - e * 23);       // 1..23
            if (blk0 + e < nbatch) {
                const float* src = lqb + e * (JN * 4) + j * 4;
                unsigned int dst = sq_base + (unsigned int)(e * 23 + (j - 1)) * 16u;
                cp_async16(dst, src);
            }
        }
        asm volatile("cp.async.commit_group;" ::: "memory");
    }

    // ---- Direct loads that overlap the async transfer ----
    float blv[JN];
    float gq0w, gq0x, gq0y, gq0z, gp0x, gp0y, gp0z;
    if (active) {
        const float* blb = bl + (size_t)b * JN;
        ldg256(blb,      blv);
        ldg256(blb + 8,  blv + 8);
        ldg256(blb + 16, blv + 16);

        float4 rq = rootq[b];
        float s   = rq.x*rq.x + rq.y*rq.y + rq.z*rq.z + rq.w*rq.w;
        float inv = rsqrtf(s);
        gq0w = rq.x * inv; gq0x = rq.y * inv; gq0y = rq.z * inv; gq0z = rq.w * inv;

        gp0x = rootp[3 * b + 0];
        gp0y = rootp[3 * b + 1];
        gp0z = rootp[3 * b + 2];
    }

    asm volatile("cp.async.wait_group 0;" ::: "memory");
    __syncthreads();

    if (!active) return;

    const int PAR[JN] = {-1,0,0,0,1,2,3,4,5,6,7,8,9,9,9,12,13,14,16,17,18,19,20,21};

    float gqw[JN], gqx[JN], gqy[JN], gqz[JN];
    float gpx[JN], gpy[JN], gpz[JN];
    gqw[0] = gq0w; gqx[0] = gq0x; gqy[0] = gq0y; gqz[0] = gq0z;
    gpx[0] = gp0x; gpy[0] = gp0y; gpz[0] = gp0z;

    // Rolling 8-float output buffer -> one st.global.v8.f32 per 8 floats.
    float sb[8];
    float* ob = out + (size_t)b * (JN * 3);

    #define EMIT(o, v)                                 \
        do {                                           \
            sb[(o) & 7] = (v);                         \
            if (((o) & 7) == 7)                        \
                stg256(ob + ((o) & ~7), sb);           \
        } while (0)

    EMIT(0, gpx[0]);
    EMIT(1, gpy[0]);
    EMIT(2, gpz[0]);

    const float4* qrow = sq + tid * 23;

    #pragma unroll
    for (int j = 1; j < JN; j++) {
        const int p = PAR[j];

        // Normalize local quat for joint j (from smem), single MUFU.RSQ.
        float4 c4 = qrow[j - 1];
        float s   = c4.x*c4.x + c4.y*c4.y + c4.z*c4.z + c4.w*c4.w;
        float inv = rsqrtf(s);
        float cw = c4.x * inv, cx = c4.y * inv, cy = c4.z * inv, cz = c4.w * inv;

        // Parent global quat.
        float pw = gqw[p], px = gqx[p], py = gqy[p], pz = gqz[p];

        // Global quat for j = parent . local.
        gqw[j] = pw*cw - px*cx - py*cy - pz*cz;
        gqx[j] = pw*cx + px*cw + py*cz - pz*cy;
        gqy[j] = pw*cy - px*cz + py*cw + pz*cx;
        gqz[j] = pw*cz + px*cy - py*cx + pz*cw;

        // Rotate rest direction d[j] by the PARENT quat.
        float dx = sdir[3*j + 0], dy = sdir[3*j + 1], dz = sdir[3*j + 2];
        float tx = 2.0f * (py*dz - pz*dy);
        float ty = 2.0f * (pz*dx - px*dz);
        float tz = 2.0f * (px*dy - py*dx);
        float rx = dx + pw*tx + (py*tz - pz*ty);
        float ry = dy + pw*ty + (pz*tx - px*tz);
        float rz = dz + pw*tz + (px*ty - py*tx);

        float L = blv[j];
        gpx[j] = gpx[p] + rx * L;
        gpy[j] = gpy[p] + ry * L;
        gpz[j] = gpz[p] + rz * L;

        EMIT(3*j + 0, gpx[j]);
        EMIT(3*j + 1, gpy[j]);
        EMIT(3*j + 2, gpz[j]);
    }
    #undef EMIT
}

extern "C" void kernel_launch(void* const* d_in, const int* in_sizes, int n_in,
                              void* d_out, int out_size)
{
    // metadata order: root_orientation_quat [B,4], root_position [B,3],
    //                 local_joint_rotations_quat [B,J,4], bone_lengths [B,J],
    //                 rest_directions [J,3]
    const float4* rootq  = (const float4*)d_in[0];
    const float*  rootp  = (const float*)d_in[1];
    const float*  localq = (const float*)d_in[2];
    const float*  bl     = (const float*)d_in[3];
    const float*  restd  = (const float*)d_in[4];
    float*        out    = (float*)d_out;

    int nbatch = in_sizes[1] / 3;   // root_position has B*3 elements

    int blocks = (nbatch + TPB - 1) / TPB;
    fk_kernel<<<blocks, TPB>>>(rootq, rootp, localq, bl, restd, out, nbatch);
}

// round 17
// speedup vs baseline: 1.0562x; 1.0562x over previous
#include <cuda_runtime.h>
#include <cstdint>
#include <math.h>

#define JN 24
#define EPSF 1e-8f
#define TPB 128

// R17 = R15 (best, 66.3us) + two issue-side cuts, shape unchanged:
//  1. bl/root LDGs issued BEFORE the 23-LDGSTS staging burst (LDGSTS rt=8
//     occupies the LSU ~184cyc/warp; LDGs now get their ~600cyc DRAM
//     latency started first instead of queuing behind the burst).
//  2. Unpredicated staging fast path for full tiles (B = 4096*128 exactly,
//     so every tile is full): removes 23 predicates + bound checks per
//     thread from the hot path.
// Body otherwise identical: cp.async staging (47.1KB, 4 CTAs/SM), rsqrt
// normalization, v8 bl loads, rolling-8 v8 output stores.

__device__ __forceinline__ void stg256(float* p, const float* v) {
    asm volatile(
        "st.global.v8.f32 [%0], {%1,%2,%3,%4,%5,%6,%7,%8};"
        :: "l"(p),
           "f"(v[0]), "f"(v[1]), "f"(v[2]), "f"(v[3]),
           "f"(v[4]), "f"(v[5]), "f"(v[6]), "f"(v[7])
        : "memory");
}

__device__ __forceinline__ void ldg256(const float* p, float* v) {
    asm(
        "ld.global.v8.f32 {%0,%1,%2,%3,%4,%5,%6,%7}, [%8];"
        : "=f"(v[0]), "=f"(v[1]), "=f"(v[2]), "=f"(v[3]),
          "=f"(v[4]), "=f"(v[5]), "=f"(v[6]), "=f"(v[7])
        : "l"(p));
}

__device__ __forceinline__ void cp_async16(unsigned int smem_dst, const void* gsrc) {
    asm volatile("cp.async.cg.shared.global [%0], [%1], 16;"
                 :: "r"(smem_dst), "l"(gsrc) : "memory");
}

__global__ __launch_bounds__(TPB) void fk_kernel(
    const float4* __restrict__ rootq,   // [B,4]  (w,x,y,z)
    const float*  __restrict__ rootp,   // [B,3]
    const float*  __restrict__ localq,  // [B,J,4] as floats
    const float*  __restrict__ bl,      // [B,J]
    const float*  __restrict__ restd,   // [J,3]
    float*        __restrict__ out,     // [B,J,3]
    int nbatch)
{
    __shared__ float4 sq[TPB * 23];     // quats 1..23 per element, 368B rows
    __shared__ float  sdir[JN * 3];

    const int tid = threadIdx.x;
    if (tid < JN * 3) sdir[tid] = restd[tid];

    const int blk0 = blockIdx.x * TPB;
    const int b    = blk0 + tid;
    const bool active = (b < nbatch);

    // ---- (1) Direct loads FIRST so their DRAM latency starts before the
    //      LSU is occupied by the LDGSTS burst. Regs have headroom
    //      (occupancy is smem-bound at 4 CTAs/SM).
    float blv[JN];
    float gq0w, gq0x, gq0y, gq0z, gp0x, gp0y, gp0z;
    if (active) {
        const float* blb = bl + (size_t)b * JN;
        ldg256(blb,      blv);
        ldg256(blb + 8,  blv + 8);
        ldg256(blb + 16, blv + 16);

        float4 rq = rootq[b];
        float s   = rq.x*rq.x + rq.y*rq.y + rq.z*rq.z + rq.w*rq.w;
        float inv = rsqrtf(s);
        gq0w = rq.x * inv; gq0x = rq.y * inv; gq0y = rq.z * inv; gq0z = rq.w * inv;

        gp0x = rootp[3 * b + 0];
        gp0y = rootp[3 * b + 1];
        gp0z = rootp[3 * b + 2];
    }

    // ---- Stage local quats 1..23 for all TPB elements via cp.async ----
    {
        unsigned int sq_base;
        asm("{ .reg .u64 t; cvta.to.shared.u64 t, %1; cvt.u32.u64 %0, t; }"
            : "=r"(sq_base) : "l"(sq));
        const float* lqb = localq + (size_t)blk0 * (JN * 4);

        if (blk0 + TPB <= nbatch) {
            // (2) Full tile: no predicates.
            #pragma unroll
            for (int k = 0; k < 23; k++) {
                int g = tid + k * TPB;          // 0..2943
                int e = g / 23;
                int j = 1 + (g - e * 23);       // 1..23
                cp_async16(sq_base + (unsigned int)(e * 23 + (j - 1)) * 16u,
                           lqb + e * (JN * 4) + j * 4);
            }
        } else {
            #pragma unroll
            for (int k = 0; k < 23; k++) {
                int g = tid + k * TPB;
                int e = g / 23;
                int j = 1 + (g - e * 23);
                if (blk0 + e < nbatch)
                    cp_async16(sq_base + (unsigned int)(e * 23 + (j - 1)) * 16u,
                               lqb + e * (JN * 4) + j * 4);
            }
        }
        asm volatile("cp.async.commit_group;" ::: "memory");
    }

    asm volatile("cp.async.wait_group 0;" ::: "memory");
    __syncthreads();

    if (!active) return;

    const int PAR[JN] = {-1,0,0,0,1,2,3,4,5,6,7,8,9,9,9,12,13,14,16,17,18,19,20,21};

    float gqw[JN], gqx[JN], gqy[JN], gqz[JN];
    float gpx[JN], gpy[JN], gpz[JN];
    gqw[0] = gq0w; gqx[0] = gq0x; gqy[0] = gq0y; gqz[0] = gq0z;
    gpx[0] = gp0x; gpy[0] = gp0y; gpz[0] = gp0z;

    // Rolling 8-float output buffer -> one st.global.v8.f32 per 8 floats.
    float sb[8];
    float* ob = out + (size_t)b * (JN * 3);

    #define EMIT(o, v)                                 \
        do {                                           \
            sb[(o) & 7] = (v);                         \
            if (((o) & 7) == 7)                        \
                stg256(ob + ((o) & ~7), sb);           \
        } while (0)

    EMIT(0, gpx[0]);
    EMIT(1, gpy[0]);
    EMIT(2, gpz[0]);

    const float4* qrow = sq + tid * 23;

    #pragma unroll
    for (int j = 1; j < JN; j++) {
        const int p = PAR[j];

        // Normalize local quat for joint j (from smem), single MUFU.RSQ.
        float4 c4 = qrow[j - 1];
        float s   = c4.x*c4.x + c4.y*c4.y + c4.z*c4.z + c4.w*c4.w;
        float inv = rsqrtf(s);
        float cw = c4.x * inv, cx = c4.y * inv, cy = c4.z * inv, cz = c4.w * inv;

        // Parent global quat.
        float pw = gqw[p], px = gqx[p], py = gqy[p], pz = gqz[p];

        // Global quat for j = parent . local.
        gqw[j] = pw*cw - px*cx - py*cy - pz*cz;
        gqx[j] = pw*cx + px*cw + py*cz - pz*cy;
        gqy[j] = pw*cy - px*cz + py*cw + pz*cx;
        gqz[j] = pw*cz + px*cy - py*cx + pz*cw;

        // Rotate rest direction d[j] by the PARENT quat.
        float dx = sdir[3*j + 0], dy = sdir[3*j + 1], dz = sdir[3*j + 2];
        float tx = 2.0f * (py*dz - pz*dy);
        float ty = 2.0f * (pz*dx - px*dz);
        float tz = 2.0f * (px*dy - py*dx);
        float rx = dx + pw*tx + (py*tz - pz*ty);
        float ry = dy + pw*ty + (pz*tx - px*tz);
        float rz = dz + pw*tz + (px*ty - py*tx);

        float L = blv[j];
        gpx[j] = gpx[p] + rx * L;
        gpy[j] = gpy[p] + ry * L;
        gpz[j] = gpz[p] + rz * L;

        EMIT(3*j + 0, gpx[j]);
        EMIT(3*j + 1, gpy[j]);
        EMIT(3*j + 2, gpz[j]);
    }
    #undef EMIT
}

extern "C" void kernel_launch(void* const* d_in, const int* in_sizes, int n_in,
                              void* d_out, int out_size)
{
    // metadata order: root_orientation_quat [B,4], root_position [B,3],
    //                 local_joint_rotations_quat [B,J,4], bone_lengths [B,J],
    //                 rest_directions [J,3]
    const float4* rootq  = (const float4*)d_in[0];
    const float*  rootp  = (const float*)d_in[1];
    const float*  localq = (const float*)d_in[2];
    const float*  bl     = (const float*)d_in[3];
    const float*  restd  = (const float*)d_in[4];
    float*        out    = (float*)d_out;

    int nbatch = in_sizes[1] / 3;   // root_position has B*3 elements

    int blocks = (nbatch + TPB - 1) / TPB;
    fk_kernel<<<blocks, TPB>>>(rootq, rootp, localq, bl, restd, out, nbatch);
}